// round 1
// baseline (speedup 1.0000x reference)
#include <cuda_runtime.h>

#define BB 128  // batch, innermost contiguous dim everywhere

// ---------------- scratch (device globals, allocation-free) ----------------
__device__ __align__(16) float g_bin[9 * 32 * 32 * BB];     // binarized, CHWB
__device__ __align__(16) float g_h1[32 * 16 * 16 * BB];     // after conv1+pool
__device__ __align__(16) float g_h2[128 * 8 * 8 * BB];      // after conv2+pool
__device__ __align__(16) float g_h3[512 * 4 * 4 * BB];      // after conv3+pool
__device__ __align__(16) float g_h4[4096 * BB];             // after conv4+pool == flatten [D,B]
__device__ __align__(16) float g_g1[40960 * BB];            // logic1 out
__device__ __align__(16) float g_g2[20480 * BB];            // logic2 out
__device__ __align__(16) float g_mix[83552 * 4];            // mixed gate coefs, 4 per node
__device__ __align__(16) float g_part[160 * BB];            // l3 partial class sums

// GATE_COEF (16 x 4)
__constant__ float GC[64] = {
    0, 0, 0, 0,   0, 0, 0, 1,   0, 1, 0, -1,  0, 1, 0, 0,
    0, 0, 1, -1,  0, 0, 1, 0,   0, 1, 1, -2,  0, 1, 1, -1,
    1, -1, -1, 1, 1, -1, -1, 2, 1, 0, -1, 0,  1, 0, -1, 1,
    1, -1, 0, 0,  1, -1, 0, 1,  1, 0, 0, -1,  1, 0, 0, 0};

// node-offsets into g_mix (units of nodes)
// c1=32*7, c2=128*7, c3=512*7, c4=1024*7, l1=40960, l2=20480, l3=10240
#define OFF_C1 0
#define OFF_C2 224
#define OFF_C3 1120
#define OFF_C4 4704
#define OFF_L1 11872
#define OFF_L2 52832
#define OFF_L3 73312
#define N_NODES 83552

// ---------------- kernel 1: softmax(logits) @ GATE_COEF for every node ------
__global__ void mix_kernel(const float* __restrict__ s0, const float* __restrict__ s1,
                           const float* __restrict__ s2, const float* __restrict__ s3,
                           const float* __restrict__ s4, const float* __restrict__ s5,
                           const float* __restrict__ s6, float* __restrict__ dst) {
    int tid = blockIdx.x * blockDim.x + threadIdx.x;
    if (tid >= N_NODES) return;
    const int offs[8] = {OFF_C1, OFF_C2, OFF_C3, OFF_C4, OFF_L1, OFF_L2, OFF_L3, N_NODES};
    const float* srcs[7] = {s0, s1, s2, s3, s4, s5, s6};
    int seg = 0;
    while (tid >= offs[seg + 1]) seg++;
    const float* w = srcs[seg] + (size_t)(tid - offs[seg]) * 16;

    float e[16];
    float mx = w[0];
#pragma unroll
    for (int i = 1; i < 16; i++) mx = fmaxf(mx, w[i]);
    float s = 0.f;
#pragma unroll
    for (int i = 0; i < 16; i++) { e[i] = expf(w[i] - mx); s += e[i]; }
    float inv = 1.f / s;
    float m0 = 0.f, m1 = 0.f, m2 = 0.f, m3 = 0.f;
#pragma unroll
    for (int i = 0; i < 16; i++) {
        float p = e[i] * inv;
        m0 = fmaf(p, GC[i * 4 + 0], m0);
        m1 = fmaf(p, GC[i * 4 + 1], m1);
        m2 = fmaf(p, GC[i * 4 + 2], m2);
        m3 = fmaf(p, GC[i * 4 + 3], m3);
    }
    float4 o; o.x = m0; o.y = m1; o.z = m2; o.w = m3;
    ((float4*)dst)[tid] = o;
}

// ---------------- kernel 2: binarize + BCHW -> CHWB transpose --------------
__global__ void binarize_kernel(const float* __restrict__ x, float* __restrict__ bin) {
    __shared__ float tile[32][33];
    int c = blockIdx.z;        // 0..2
    int h = blockIdx.y;        // 0..31
    int bc = blockIdx.x;       // 0..3 (batch chunks of 32)
    int b = bc * 32 + threadIdx.y;
    // coalesced read along w
    tile[threadIdx.y][threadIdx.x] = x[(((size_t)b * 3 + c) * 32 + h) * 32 + threadIdx.x];
    __syncthreads();
    int w = threadIdx.y;
    int bout = bc * 32 + threadIdx.x;
    float v = tile[threadIdx.x][w];
    const float thr[3] = {0.25f, 0.5f, 0.75f};
#pragma unroll
    for (int t = 0; t < 3; t++) {
        // coalesced write along b
        bin[((((size_t)(t * 3 + c)) * 32 + h) * 32 + w) * BB + bout] = (v > thr[t]) ? 1.f : 0.f;
    }
}

__device__ __forceinline__ float gate4(float a, float b, const float* w) {
    return w[0] + w[1] * a + w[2] * b + w[3] * (a * b);
}

// ---------------- kernel 3-6: tree_conv + or_pool fused (CHWB layout) ------
__global__ void __launch_bounds__(128) tree_conv_kernel(
    const float* __restrict__ in, float* __restrict__ out,
    const int* __restrict__ leaf, const float* __restrict__ mix, int Hin) {
    int o = blockIdx.y;
    int tid = threadIdx.x;  // batch lane
    __shared__ float sm[28];
    __shared__ int sch[8], sdy[8], sdx[8];
    if (tid < 28) sm[tid] = mix[o * 28 + tid];
    if (tid < 8) {
        int idx = leaf[o * 8 + tid];
        sch[tid] = idx / 9;
        int p = idx % 9;
        sdy[tid] = p / 3 - 1;
        sdx[tid] = p % 3 - 1;
    }
    __syncthreads();
    int Wo = Hin >> 1;
    int s = blockIdx.x;            // output spatial index, Ho*Wo
    int wo = s % Wo, ho = s / Wo;

    float r = -1e30f;
#pragma unroll
    for (int ph = 0; ph < 2; ph++) {
#pragma unroll
        for (int pw = 0; pw < 2; pw++) {
            int y = 2 * ho + ph, xx = 2 * wo + pw;
            float v[8];
#pragma unroll
            for (int l = 0; l < 8; l++) {
                int yy = y + sdy[l], x2 = xx + sdx[l];
                bool ok = ((unsigned)yy < (unsigned)Hin) && ((unsigned)x2 < (unsigned)Hin);
                v[l] = ok ? in[(((size_t)sch[l] * Hin + yy) * Hin + x2) * BB + tid] : 0.f;
            }
            float t0 = gate4(v[0], v[1], sm + 0);
            float t1 = gate4(v[2], v[3], sm + 4);
            float t2 = gate4(v[4], v[5], sm + 8);
            float t3 = gate4(v[6], v[7], sm + 12);
            float u0 = gate4(t0, t1, sm + 16);
            float u1 = gate4(t2, t3, sm + 20);
            float z = gate4(u0, u1, sm + 24);
            r = fmaxf(r, z);
        }
    }
    out[((size_t)o * Wo * Wo + s) * BB + tid] = r;
}

// ---------------- kernels 7-8: logic layers ([D,B] layout) -----------------
__global__ void logic_kernel(const float* __restrict__ in, float* __restrict__ out,
                             const int* __restrict__ ai, const int* __restrict__ bi,
                             const float* __restrict__ mix, int Dout) {
    int tid = blockIdx.x * blockDim.x + threadIdx.x;
    if (tid >= Dout * BB) return;
    int j = tid >> 7, b = tid & 127;
    float4 w = ((const float4*)mix)[j];
    float av = in[(size_t)ai[j] * BB + b];
    float bv = in[(size_t)bi[j] * BB + b];
    out[tid] = w.x + w.y * av + w.z * bv + w.w * (av * bv);
}

// ---------------- kernel 9: logic3 fused with group-sum partials -----------
// 160 blocks; block blk handles 64 consecutive j (all within one class).
__global__ void __launch_bounds__(128) logic3_sum_kernel(
    const float* __restrict__ in, float* __restrict__ part,
    const int* __restrict__ ai, const int* __restrict__ bi,
    const float* __restrict__ mix) {
    int blk = blockIdx.x;
    int j0 = blk * 64;
    int b = threadIdx.x;
    float acc = 0.f;
#pragma unroll 4
    for (int jj = 0; jj < 64; jj++) {
        int j = j0 + jj;
        float4 w = ((const float4*)mix)[j];
        float av = in[(size_t)ai[j] * BB + b];
        float bv = in[(size_t)bi[j] * BB + b];
        acc += w.x + w.y * av + w.z * bv + w.w * (av * bv);
    }
    part[(size_t)blk * BB + b] = acc;
}

// ---------------- kernel 10: final reduce, [B,10] output -------------------
__global__ void final_sum_kernel(const float* __restrict__ part, float* __restrict__ out) {
    int tid = blockIdx.x * blockDim.x + threadIdx.x;  // 1280 = 10 cls * 128 b
    if (tid >= 1280) return;
    int cls = tid >> 7, b = tid & 127;
    float s = 0.f;
#pragma unroll
    for (int k = 0; k < 16; k++) s += part[(size_t)(cls * 16 + k) * BB + b];
    out[b * 10 + cls] = s * 0.01f;  // / TAU
}

// ---------------- host launcher --------------------------------------------
extern "C" void kernel_launch(void* const* d_in, const int* in_sizes, int n_in,
                              void* d_out, int out_size) {
    const float* x   = (const float*)d_in[0];
    const int*   c1i = (const int*)d_in[1];  const float* c1w = (const float*)d_in[2];
    const int*   c2i = (const int*)d_in[3];  const float* c2w = (const float*)d_in[4];
    const int*   c3i = (const int*)d_in[5];  const float* c3w = (const float*)d_in[6];
    const int*   c4i = (const int*)d_in[7];  const float* c4w = (const float*)d_in[8];
    const int*   l1a = (const int*)d_in[9];  const int* l1b = (const int*)d_in[10];
    const float* l1w = (const float*)d_in[11];
    const int*   l2a = (const int*)d_in[12]; const int* l2b = (const int*)d_in[13];
    const float* l2w = (const float*)d_in[14];
    const int*   l3a = (const int*)d_in[15]; const int* l3b = (const int*)d_in[16];
    const float* l3w = (const float*)d_in[17];

    float *bin, *h1, *h2, *h3, *h4, *g1, *g2, *mixb, *part;
    cudaGetSymbolAddress((void**)&bin,  g_bin);
    cudaGetSymbolAddress((void**)&h1,   g_h1);
    cudaGetSymbolAddress((void**)&h2,   g_h2);
    cudaGetSymbolAddress((void**)&h3,   g_h3);
    cudaGetSymbolAddress((void**)&h4,   g_h4);
    cudaGetSymbolAddress((void**)&g1,   g_g1);
    cudaGetSymbolAddress((void**)&g2,   g_g2);
    cudaGetSymbolAddress((void**)&mixb, g_mix);
    cudaGetSymbolAddress((void**)&part, g_part);

    // 1. gate mixing for all 83552 nodes
    mix_kernel<<<(N_NODES + 127) / 128, 128>>>(c1w, c2w, c3w, c4w, l1w, l2w, l3w, mixb);
    // 2. binarize + transpose to CHWB
    binarize_kernel<<<dim3(4, 32, 3), dim3(32, 32)>>>(x, bin);
    // 3-6. tree_conv + or_pool, CHWB -> CHWB
    tree_conv_kernel<<<dim3(256, 32),  128>>>(bin, h1, c1i, mixb + OFF_C1 * 4, 32);
    tree_conv_kernel<<<dim3(64, 128),  128>>>(h1,  h2, c2i, mixb + OFF_C2 * 4, 16);
    tree_conv_kernel<<<dim3(16, 512),  128>>>(h2,  h3, c3i, mixb + OFF_C3 * 4, 8);
    tree_conv_kernel<<<dim3(4, 1024),  128>>>(h3,  h4, c4i, mixb + OFF_C4 * 4, 4);
    // 7-8. logic layers
    logic_kernel<<<(40960 * BB) / 256, 256>>>(h4, g1, l1a, l1b, mixb + OFF_L1 * 4, 40960);
    logic_kernel<<<(20480 * BB) / 256, 256>>>(g1, g2, l2a, l2b, mixb + OFF_L2 * 4, 20480);
    // 9. logic3 fused with group-sum partials
    logic3_sum_kernel<<<160, 128>>>(g2, part, l3a, l3b, mixb + OFF_L3 * 4);
    // 10. final reduce -> [B, 10]
    final_sum_kernel<<<10, 128>>>(part, (float*)d_out);
}

// round 2
// speedup vs baseline: 2.4809x; 2.4809x over previous
#include <cuda_runtime.h>

#define BB 128  // batch
#define BV 32   // batch in float4 units

// ---------------- scratch (device globals) ----------------
__device__ __align__(16) float g_bin[9 * 32 * 32 * BB];
__device__ __align__(16) float g_h1[32 * 16 * 16 * BB];
__device__ __align__(16) float g_h2[128 * 8 * 8 * BB];
__device__ __align__(16) float g_h3[512 * 4 * 4 * BB];
__device__ __align__(16) float g_h4[4096 * BB];
__device__ __align__(16) float g_g1[40960 * BB];
__device__ __align__(16) float g_g2[20480 * BB];
__device__ __align__(16) float g_mix[83552 * 4];
__device__ __align__(16) float g_part[160 * BB];

__constant__ float GC[64] = {
    0, 0, 0, 0,   0, 0, 0, 1,   0, 1, 0, -1,  0, 1, 0, 0,
    0, 0, 1, -1,  0, 0, 1, 0,   0, 1, 1, -2,  0, 1, 1, -1,
    1, -1, -1, 1, 1, -1, -1, 2, 1, 0, -1, 0,  1, 0, -1, 1,
    1, -1, 0, 0,  1, -1, 0, 1,  1, 0, 0, -1,  1, 0, 0, 0};

#define OFF_C1 0
#define OFF_C2 224
#define OFF_C3 1120
#define OFF_C4 4704
#define OFF_L1 11872
#define OFF_L2 52832
#define OFF_L3 73312
#define N_NODES 83552

// ---------------- float4 helpers ----------------
__device__ __forceinline__ float4 f4(float v) { return make_float4(v, v, v, v); }
__device__ __forceinline__ float4 gate4v(float4 a, float4 b, float w0, float w1, float w2, float w3) {
    float4 r;
    r.x = fmaf(w3, a.x * b.x, fmaf(w2, b.x, fmaf(w1, a.x, w0)));
    r.y = fmaf(w3, a.y * b.y, fmaf(w2, b.y, fmaf(w1, a.y, w0)));
    r.z = fmaf(w3, a.z * b.z, fmaf(w2, b.z, fmaf(w1, a.z, w0)));
    r.w = fmaf(w3, a.w * b.w, fmaf(w2, b.w, fmaf(w1, a.w, w0)));
    return r;
}
__device__ __forceinline__ float4 max4(float4 a, float4 b) {
    return make_float4(fmaxf(a.x, b.x), fmaxf(a.y, b.y), fmaxf(a.z, b.z), fmaxf(a.w, b.w));
}

// ---------------- kernel 1: gate mixing ----------------
__global__ void mix_kernel(const float* __restrict__ s0, const float* __restrict__ s1,
                           const float* __restrict__ s2, const float* __restrict__ s3,
                           const float* __restrict__ s4, const float* __restrict__ s5,
                           const float* __restrict__ s6, float* __restrict__ dst) {
    int tid = blockIdx.x * blockDim.x + threadIdx.x;
    if (tid >= N_NODES) return;
    const int offs[8] = {OFF_C1, OFF_C2, OFF_C3, OFF_C4, OFF_L1, OFF_L2, OFF_L3, N_NODES};
    const float* srcs[7] = {s0, s1, s2, s3, s4, s5, s6};
    int seg = 0;
    while (tid >= offs[seg + 1]) seg++;
    const float* w = srcs[seg] + (size_t)(tid - offs[seg]) * 16;

    float e[16];
    float mx = w[0];
#pragma unroll
    for (int i = 1; i < 16; i++) mx = fmaxf(mx, w[i]);
    float s = 0.f;
#pragma unroll
    for (int i = 0; i < 16; i++) { e[i] = expf(w[i] - mx); s += e[i]; }
    float inv = 1.f / s;
    float m0 = 0.f, m1 = 0.f, m2 = 0.f, m3 = 0.f;
#pragma unroll
    for (int i = 0; i < 16; i++) {
        float p = e[i] * inv;
        m0 = fmaf(p, GC[i * 4 + 0], m0);
        m1 = fmaf(p, GC[i * 4 + 1], m1);
        m2 = fmaf(p, GC[i * 4 + 2], m2);
        m3 = fmaf(p, GC[i * 4 + 3], m3);
    }
    float4 o; o.x = m0; o.y = m1; o.z = m2; o.w = m3;
    ((float4*)dst)[tid] = o;
}

// ---------------- kernel 2: binarize + BCHW -> CHWB ----------------
__global__ void binarize_kernel(const float* __restrict__ x, float* __restrict__ bin) {
    __shared__ float tile[32][33];
    int c = blockIdx.z;
    int h = blockIdx.y;
    int bc = blockIdx.x;
    int b = bc * 32 + threadIdx.y;
    tile[threadIdx.y][threadIdx.x] = x[(((size_t)b * 3 + c) * 32 + h) * 32 + threadIdx.x];
    __syncthreads();
    int w = threadIdx.y;
    int bout = bc * 32 + threadIdx.x;
    float v = tile[threadIdx.x][w];
    const float thr[3] = {0.25f, 0.5f, 0.75f};
#pragma unroll
    for (int t = 0; t < 3; t++) {
        bin[((((size_t)(t * 3 + c)) * 32 + h) * 32 + w) * BB + bout] = (v > thr[t]) ? 1.f : 0.f;
    }
}

// ---------------- tree_conv + or_pool, float4 over batch, templated Hin ----
template <int Hin, int SPB>
__global__ void __launch_bounds__(32 * SPB) tree_conv_kernel(
    const float4* __restrict__ in, float4* __restrict__ out,
    const int* __restrict__ leaf, const float* __restrict__ mix) {
    constexpr int Wo = Hin / 2;
    int o = blockIdx.y;
    __shared__ float sm[28];
    __shared__ int sbase[8], sdy[8], sdx[8];
    int t = threadIdx.y * 32 + threadIdx.x;
    if (t < 28) sm[t] = mix[o * 28 + t];
    if (t < 8) {
        int idx = leaf[o * 8 + t];
        int ch = idx / 9, p = idx % 9;
        sbase[t] = ch * Hin * Hin;
        sdy[t] = p / 3 - 1;
        sdx[t] = p % 3 - 1;
    }
    __syncthreads();
    int s = blockIdx.x * SPB + threadIdx.y;
    int wo = s % Wo, ho = s / Wo;
    int lane = threadIdx.x;

    float4 r = f4(-1e30f);
#pragma unroll
    for (int ph = 0; ph < 2; ph++) {
#pragma unroll
        for (int pw = 0; pw < 2; pw++) {
            int y = 2 * ho + ph, xx = 2 * wo + pw;
            float4 v[8];
#pragma unroll
            for (int l = 0; l < 8; l++) {
                int yy = y + sdy[l], x2 = xx + sdx[l];
                bool ok = ((unsigned)yy < (unsigned)Hin) & ((unsigned)x2 < (unsigned)Hin);
                v[l] = ok ? in[(size_t)(sbase[l] + yy * Hin + x2) * BV + lane] : f4(0.f);
            }
            float4 t0 = gate4v(v[0], v[1], sm[0], sm[1], sm[2], sm[3]);
            float4 t1 = gate4v(v[2], v[3], sm[4], sm[5], sm[6], sm[7]);
            float4 t2 = gate4v(v[4], v[5], sm[8], sm[9], sm[10], sm[11]);
            float4 t3 = gate4v(v[6], v[7], sm[12], sm[13], sm[14], sm[15]);
            float4 u0 = gate4v(t0, t1, sm[16], sm[17], sm[18], sm[19]);
            float4 u1 = gate4v(t2, t3, sm[20], sm[21], sm[22], sm[23]);
            float4 z  = gate4v(u0, u1, sm[24], sm[25], sm[26], sm[27]);
            r = max4(r, z);
        }
    }
    out[((size_t)o * Wo * Wo + s) * BV + lane] = r;
}

// ---------------- logic layers, float4 over batch ----------------
__global__ void logic_kernel(const float4* __restrict__ in, float4* __restrict__ out,
                             const int* __restrict__ ai, const int* __restrict__ bi,
                             const float4* __restrict__ mix, int Dout) {
    int tid = blockIdx.x * blockDim.x + threadIdx.x;
    if (tid >= Dout * BV) return;
    int j = tid >> 5, lane = tid & 31;
    float4 w = mix[j];
    float4 a = in[(size_t)__ldg(&ai[j]) * BV + lane];
    float4 b = in[(size_t)__ldg(&bi[j]) * BV + lane];
    out[tid] = gate4v(a, b, w.x, w.y, w.z, w.w);
}

// ---------------- logic3 fused with group-sum partials ----------------
__global__ void __launch_bounds__(32) logic3_sum_kernel(
    const float4* __restrict__ in, float4* __restrict__ part,
    const int* __restrict__ ai, const int* __restrict__ bi,
    const float4* __restrict__ mix) {
    int blk = blockIdx.x;
    int j0 = blk * 64;
    int lane = threadIdx.x;
    float4 acc = f4(0.f);
#pragma unroll 4
    for (int jj = 0; jj < 64; jj++) {
        int j = j0 + jj;
        float4 w = mix[j];
        float4 a = in[(size_t)__ldg(&ai[j]) * BV + lane];
        float4 b = in[(size_t)__ldg(&bi[j]) * BV + lane];
        float4 g = gate4v(a, b, w.x, w.y, w.z, w.w);
        acc.x += g.x; acc.y += g.y; acc.z += g.z; acc.w += g.w;
    }
    part[(size_t)blk * BV + lane] = acc;
}

// ---------------- final reduce ----------------
__global__ void final_sum_kernel(const float* __restrict__ part, float* __restrict__ out) {
    int tid = blockIdx.x * blockDim.x + threadIdx.x;
    if (tid >= 1280) return;
    int cls = tid >> 7, b = tid & 127;
    float s = 0.f;
#pragma unroll
    for (int k = 0; k < 16; k++) s += part[(size_t)(cls * 16 + k) * BB + b];
    out[b * 10 + cls] = s * 0.01f;
}

// ---------------- host launcher ----------------
extern "C" void kernel_launch(void* const* d_in, const int* in_sizes, int n_in,
                              void* d_out, int out_size) {
    const float* x   = (const float*)d_in[0];
    const int*   c1i = (const int*)d_in[1];  const float* c1w = (const float*)d_in[2];
    const int*   c2i = (const int*)d_in[3];  const float* c2w = (const float*)d_in[4];
    const int*   c3i = (const int*)d_in[5];  const float* c3w = (const float*)d_in[6];
    const int*   c4i = (const int*)d_in[7];  const float* c4w = (const float*)d_in[8];
    const int*   l1a = (const int*)d_in[9];  const int* l1b = (const int*)d_in[10];
    const float* l1w = (const float*)d_in[11];
    const int*   l2a = (const int*)d_in[12]; const int* l2b = (const int*)d_in[13];
    const float* l2w = (const float*)d_in[14];
    const int*   l3a = (const int*)d_in[15]; const int* l3b = (const int*)d_in[16];
    const float* l3w = (const float*)d_in[17];

    float *bin, *h1, *h2, *h3, *h4, *g1, *g2, *mixb, *part;
    cudaGetSymbolAddress((void**)&bin,  g_bin);
    cudaGetSymbolAddress((void**)&h1,   g_h1);
    cudaGetSymbolAddress((void**)&h2,   g_h2);
    cudaGetSymbolAddress((void**)&h3,   g_h3);
    cudaGetSymbolAddress((void**)&h4,   g_h4);
    cudaGetSymbolAddress((void**)&g1,   g_g1);
    cudaGetSymbolAddress((void**)&g2,   g_g2);
    cudaGetSymbolAddress((void**)&mixb, g_mix);
    cudaGetSymbolAddress((void**)&part, g_part);

    mix_kernel<<<(N_NODES + 127) / 128, 128>>>(c1w, c2w, c3w, c4w, l1w, l2w, l3w, mixb);
    binarize_kernel<<<dim3(4, 32, 3), dim3(32, 32)>>>(x, bin);

    // tree_conv + pool: 32 lanes (float4 batch) x SPB spatial per block
    tree_conv_kernel<32, 8><<<dim3(32, 32),   dim3(32, 8)>>>((const float4*)bin, (float4*)h1, c1i, mixb + OFF_C1 * 4);
    tree_conv_kernel<16, 8><<<dim3(8, 128),   dim3(32, 8)>>>((const float4*)h1,  (float4*)h2, c2i, mixb + OFF_C2 * 4);
    tree_conv_kernel<8, 8> <<<dim3(2, 512),   dim3(32, 8)>>>((const float4*)h2,  (float4*)h3, c3i, mixb + OFF_C3 * 4);
    tree_conv_kernel<4, 4> <<<dim3(1, 1024),  dim3(32, 4)>>>((const float4*)h3,  (float4*)h4, c4i, mixb + OFF_C4 * 4);

    logic_kernel<<<(40960 * BV) / 256, 256>>>((const float4*)h4, (float4*)g1, l1a, l1b, (const float4*)(mixb + OFF_L1 * 4), 40960);
    logic_kernel<<<(20480 * BV) / 256, 256>>>((const float4*)g1, (float4*)g2, l2a, l2b, (const float4*)(mixb + OFF_L2 * 4), 20480);
    logic3_sum_kernel<<<160, 32>>>((const float4*)g2, (float4*)part, l3a, l3b, (const float4*)(mixb + OFF_L3 * 4));
    final_sum_kernel<<<10, 128>>>(part, (float*)d_out);
}

// round 3
// speedup vs baseline: 2.7132x; 1.0936x over previous
#include <cuda_runtime.h>

#define BB 128  // batch
#define BV 32   // batch in float4 units

// ---------------- padded geometry ----------------
// bin: 9 planes 34x34, h1: 32 planes 18x18, h2: 128 planes 10x10, h3: 512 planes 6x6
// h4 (conv4 out / flatten): 1024*2*2 unpadded.
// Halos are NEVER written by any kernel; __device__ globals are zero-init at
// context creation, so halos remain zero across all replays.
__device__ __align__(16) float g_bin[9 * 34 * 34 * BB];
__device__ __align__(16) float g_h1[32 * 18 * 18 * BB];
__device__ __align__(16) float g_h2[128 * 10 * 10 * BB];
__device__ __align__(16) float g_h3[512 * 6 * 6 * BB];
__device__ __align__(16) float g_h4[4096 * BB];
__device__ __align__(16) float g_g1[40960 * BB];
__device__ __align__(16) float g_g2[20480 * BB];
__device__ __align__(16) float g_mix[83552 * 4];
__device__ __align__(16) float g_part[160 * BB];

__constant__ float GC[64] = {
    0, 0, 0, 0,   0, 0, 0, 1,   0, 1, 0, -1,  0, 1, 0, 0,
    0, 0, 1, -1,  0, 0, 1, 0,   0, 1, 1, -2,  0, 1, 1, -1,
    1, -1, -1, 1, 1, -1, -1, 2, 1, 0, -1, 0,  1, 0, -1, 1,
    1, -1, 0, 0,  1, -1, 0, 1,  1, 0, 0, -1,  1, 0, 0, 0};

#define OFF_C1 0
#define OFF_C2 224
#define OFF_C3 1120
#define OFF_C4 4704
#define OFF_L1 11872
#define OFF_L2 52832
#define OFF_L3 73312
#define N_NODES 83552

// ---------------- float4 helpers ----------------
__device__ __forceinline__ float4 f4(float v) { return make_float4(v, v, v, v); }
__device__ __forceinline__ float4 gate4v(float4 a, float4 b, float w0, float w1, float w2, float w3) {
    float4 r;
    r.x = fmaf(w3, a.x * b.x, fmaf(w2, b.x, fmaf(w1, a.x, w0)));
    r.y = fmaf(w3, a.y * b.y, fmaf(w2, b.y, fmaf(w1, a.y, w0)));
    r.z = fmaf(w3, a.z * b.z, fmaf(w2, b.z, fmaf(w1, a.z, w0)));
    r.w = fmaf(w3, a.w * b.w, fmaf(w2, b.w, fmaf(w1, a.w, w0)));
    return r;
}
__device__ __forceinline__ float4 max4(float4 a, float4 b) {
    return make_float4(fmaxf(a.x, b.x), fmaxf(a.y, b.y), fmaxf(a.z, b.z), fmaxf(a.w, b.w));
}

// ---------------- kernel 1: gate mixing ----------------
__global__ void mix_kernel(const float* __restrict__ s0, const float* __restrict__ s1,
                           const float* __restrict__ s2, const float* __restrict__ s3,
                           const float* __restrict__ s4, const float* __restrict__ s5,
                           const float* __restrict__ s6, float* __restrict__ dst) {
    int tid = blockIdx.x * blockDim.x + threadIdx.x;
    if (tid >= N_NODES) return;
    const int offs[8] = {OFF_C1, OFF_C2, OFF_C3, OFF_C4, OFF_L1, OFF_L2, OFF_L3, N_NODES};
    const float* srcs[7] = {s0, s1, s2, s3, s4, s5, s6};
    int seg = 0;
    while (tid >= offs[seg + 1]) seg++;
    const float* w = srcs[seg] + (size_t)(tid - offs[seg]) * 16;

    float e[16];
    float mx = w[0];
#pragma unroll
    for (int i = 1; i < 16; i++) mx = fmaxf(mx, w[i]);
    float s = 0.f;
#pragma unroll
    for (int i = 0; i < 16; i++) { e[i] = __expf(w[i] - mx); s += e[i]; }
    float inv = 1.f / s;
    float m0 = 0.f, m1 = 0.f, m2 = 0.f, m3 = 0.f;
#pragma unroll
    for (int i = 0; i < 16; i++) {
        float p = e[i] * inv;
        m0 = fmaf(p, GC[i * 4 + 0], m0);
        m1 = fmaf(p, GC[i * 4 + 1], m1);
        m2 = fmaf(p, GC[i * 4 + 2], m2);
        m3 = fmaf(p, GC[i * 4 + 3], m3);
    }
    float4 o; o.x = m0; o.y = m1; o.z = m2; o.w = m3;
    ((float4*)dst)[tid] = o;
}

// ---------------- kernel 2: binarize + BCHW -> CHWB (padded out) -----------
__global__ void binarize_kernel(const float* __restrict__ x, float* __restrict__ bin) {
    __shared__ float tile[32][33];
    int c = blockIdx.z;
    int h = blockIdx.y;
    int bc = blockIdx.x;
    int b = bc * 32 + threadIdx.y;
    tile[threadIdx.y][threadIdx.x] = x[(((size_t)b * 3 + c) * 32 + h) * 32 + threadIdx.x];
    __syncthreads();
    int w = threadIdx.y;
    int bout = bc * 32 + threadIdx.x;
    float v = tile[threadIdx.x][w];
    const float thr[3] = {0.25f, 0.5f, 0.75f};
#pragma unroll
    for (int t = 0; t < 3; t++) {
        // padded plane 34x34, interior at (h+1, w+1)
        size_t idx = (((size_t)(t * 3 + c)) * 34 * 34 + (size_t)(h + 1) * 34 + (w + 1)) * BB + bout;
        bin[idx] = (v > thr[t]) ? 1.f : 0.f;
    }
}

// ---------------- tree_conv + or_pool (padded in, padded/unpadded out) -----
// Hin: logical input size. Win = Hin+2 (padded). PADOUT: pad output plane.
template <int Hin, int SPB, bool PADOUT>
__global__ void __launch_bounds__(32 * SPB, 4) tree_conv_kernel(
    const float4* __restrict__ in, float4* __restrict__ out,
    const int* __restrict__ leaf, const float* __restrict__ mix) {
    constexpr int Win = Hin + 2;
    constexpr int Wo = Hin / 2;
    constexpr int Wop = PADOUT ? (Wo + 2) : Wo;
    int o = blockIdx.y;
    __shared__ float sm[28];
    __shared__ int soff[8];  // per-leaf element offset (float4 units)
    int t = threadIdx.y * 32 + threadIdx.x;
    if (t < 28) sm[t] = mix[o * 28 + t];
    if (t < 8) {
        int idx = leaf[o * 8 + t];
        int ch = idx / 9, p = idx % 9;
        int dy = p / 3, dx = p % 3;  // 0..2 == (dy-1)+1 into padded frame
        soff[t] = (ch * Win * Win + dy * Win + dx) * BV;
    }
    __syncthreads();
    int s = blockIdx.x * SPB + threadIdx.y;
    int wo = s % Wo, ho = s / Wo;
    int lane = threadIdx.x;

    float4 r = f4(-1e30f);
#pragma unroll
    for (int ph = 0; ph < 2; ph++) {
#pragma unroll
        for (int pw = 0; pw < 2; pw++) {
            int pos = ((2 * ho + ph) * Win + (2 * wo + pw)) * BV + lane;
            float4 v[8];
#pragma unroll
            for (int l = 0; l < 8; l++) v[l] = in[soff[l] + pos];
            float4 t0 = gate4v(v[0], v[1], sm[0], sm[1], sm[2], sm[3]);
            float4 t1 = gate4v(v[2], v[3], sm[4], sm[5], sm[6], sm[7]);
            float4 t2 = gate4v(v[4], v[5], sm[8], sm[9], sm[10], sm[11]);
            float4 t3 = gate4v(v[6], v[7], sm[12], sm[13], sm[14], sm[15]);
            float4 u0 = gate4v(t0, t1, sm[16], sm[17], sm[18], sm[19]);
            float4 u1 = gate4v(t2, t3, sm[20], sm[21], sm[22], sm[23]);
            float4 z  = gate4v(u0, u1, sm[24], sm[25], sm[26], sm[27]);
            r = max4(r, z);
        }
    }
    size_t oidx;
    if (PADOUT)
        oidx = ((size_t)o * Wop * Wop + (size_t)(ho + 1) * Wop + (wo + 1)) * BV + lane;
    else
        oidx = ((size_t)o * Wo * Wo + (size_t)ho * Wo + wo) * BV + lane;
    out[oidx] = r;
}

// ---------------- logic layers ----------------
__global__ void logic_kernel(const float4* __restrict__ in, float4* __restrict__ out,
                             const int* __restrict__ ai, const int* __restrict__ bi,
                             const float4* __restrict__ mix, int Dout) {
    int tid = blockIdx.x * blockDim.x + threadIdx.x;
    if (tid >= Dout * BV) return;
    int j = tid >> 5, lane = tid & 31;
    float4 w = mix[j];
    float4 a = in[(size_t)__ldg(&ai[j]) * BV + lane];
    float4 b = in[(size_t)__ldg(&bi[j]) * BV + lane];
    out[tid] = gate4v(a, b, w.x, w.y, w.z, w.w);
}

// ---------------- logic3 fused with group-sum partials (4 warps/block) -----
__global__ void __launch_bounds__(128) logic3_sum_kernel(
    const float4* __restrict__ in, float4* __restrict__ part,
    const int* __restrict__ ai, const int* __restrict__ bi,
    const float4* __restrict__ mix) {
    __shared__ float4 red[4][32];
    int blk = blockIdx.x;
    int wz = threadIdx.y;       // warp 0..3
    int lane = threadIdx.x;
    int j0 = blk * 64 + wz * 16;
    float4 acc = f4(0.f);
#pragma unroll
    for (int jj = 0; jj < 16; jj++) {
        int j = j0 + jj;
        float4 w = mix[j];
        float4 a = in[(size_t)__ldg(&ai[j]) * BV + lane];
        float4 b = in[(size_t)__ldg(&bi[j]) * BV + lane];
        float4 g = gate4v(a, b, w.x, w.y, w.z, w.w);
        acc.x += g.x; acc.y += g.y; acc.z += g.z; acc.w += g.w;
    }
    red[wz][lane] = acc;
    __syncthreads();
    if (wz == 0) {
        float4 s = red[0][lane], s1 = red[1][lane], s2 = red[2][lane], s3 = red[3][lane];
        s.x += s1.x + s2.x + s3.x;
        s.y += s1.y + s2.y + s3.y;
        s.z += s1.z + s2.z + s3.z;
        s.w += s1.w + s2.w + s3.w;
        part[(size_t)blk * BV + lane] = s;
    }
}

// ---------------- final reduce ----------------
__global__ void final_sum_kernel(const float* __restrict__ part, float* __restrict__ out) {
    int tid = blockIdx.x * blockDim.x + threadIdx.x;
    if (tid >= 1280) return;
    int cls = tid >> 7, b = tid & 127;
    float s = 0.f;
#pragma unroll
    for (int k = 0; k < 16; k++) s += part[(size_t)(cls * 16 + k) * BB + b];
    out[b * 10 + cls] = s * 0.01f;
}

// ---------------- host launcher ----------------
extern "C" void kernel_launch(void* const* d_in, const int* in_sizes, int n_in,
                              void* d_out, int out_size) {
    const float* x   = (const float*)d_in[0];
    const int*   c1i = (const int*)d_in[1];  const float* c1w = (const float*)d_in[2];
    const int*   c2i = (const int*)d_in[3];  const float* c2w = (const float*)d_in[4];
    const int*   c3i = (const int*)d_in[5];  const float* c3w = (const float*)d_in[6];
    const int*   c4i = (const int*)d_in[7];  const float* c4w = (const float*)d_in[8];
    const int*   l1a = (const int*)d_in[9];  const int* l1b = (const int*)d_in[10];
    const float* l1w = (const float*)d_in[11];
    const int*   l2a = (const int*)d_in[12]; const int* l2b = (const int*)d_in[13];
    const float* l2w = (const float*)d_in[14];
    const int*   l3a = (const int*)d_in[15]; const int* l3b = (const int*)d_in[16];
    const float* l3w = (const float*)d_in[17];

    float *bin, *h1, *h2, *h3, *h4, *g1, *g2, *mixb, *part;
    cudaGetSymbolAddress((void**)&bin,  g_bin);
    cudaGetSymbolAddress((void**)&h1,   g_h1);
    cudaGetSymbolAddress((void**)&h2,   g_h2);
    cudaGetSymbolAddress((void**)&h3,   g_h3);
    cudaGetSymbolAddress((void**)&h4,   g_h4);
    cudaGetSymbolAddress((void**)&g1,   g_g1);
    cudaGetSymbolAddress((void**)&g2,   g_g2);
    cudaGetSymbolAddress((void**)&mixb, g_mix);
    cudaGetSymbolAddress((void**)&part, g_part);

    mix_kernel<<<(N_NODES + 127) / 128, 128>>>(c1w, c2w, c3w, c4w, l1w, l2w, l3w, mixb);
    binarize_kernel<<<dim3(4, 32, 3), dim3(32, 32)>>>(x, bin);

    tree_conv_kernel<32, 8, true> <<<dim3(32, 32),  dim3(32, 8)>>>((const float4*)bin, (float4*)h1, c1i, mixb + OFF_C1 * 4);
    tree_conv_kernel<16, 8, true> <<<dim3(8, 128),  dim3(32, 8)>>>((const float4*)h1,  (float4*)h2, c2i, mixb + OFF_C2 * 4);
    tree_conv_kernel<8, 8, true>  <<<dim3(2, 512),  dim3(32, 8)>>>((const float4*)h2,  (float4*)h3, c3i, mixb + OFF_C3 * 4);
    tree_conv_kernel<4, 4, false><<<dim3(1, 1024), dim3(32, 4)>>>((const float4*)h3,  (float4*)h4, c4i, mixb + OFF_C4 * 4);

    logic_kernel<<<(40960 * BV) / 256, 256>>>((const float4*)h4, (float4*)g1, l1a, l1b, (const float4*)(mixb + OFF_L1 * 4), 40960);
    logic_kernel<<<(20480 * BV) / 256, 256>>>((const float4*)g1, (float4*)g2, l2a, l2b, (const float4*)(mixb + OFF_L2 * 4), 20480);
    logic3_sum_kernel<<<160, dim3(32, 4)>>>((const float4*)g2, (float4*)part, l3a, l3b, (const float4*)(mixb + OFF_L3 * 4));
    final_sum_kernel<<<10, 128>>>(part, (float*)d_out);
}